// round 8
// baseline (speedup 1.0000x reference)
#include <cuda_runtime.h>
#include <cuda_bf16.h>
#include <cstdint>
#include <math.h>

#define MROWS 4096
#define CDIM  1024
#define QKVD  3072
#define HID   4096
#define SEQ   2048
#define NHEAD 16
#define HD    64

// ---------------- scratch ----------------
__device__ float g_qkv[MROWS * (size_t)QKVD];
__device__ float g_x1 [MROWS * (size_t)CDIM];
__device__ __nv_bfloat16 g_yh[MROWS*(size_t)CDIM], g_yl[MROWS*(size_t)CDIM];
__device__ __nv_bfloat16 g_ah[MROWS*(size_t)CDIM], g_al[MROWS*(size_t)CDIM];
__device__ __nv_bfloat16 g_hh[MROWS*(size_t)CDIM], g_hl[MROWS*(size_t)CDIM];
__device__ __nv_bfloat16 g_fh[MROWS*(size_t)HID],  g_fl[MROWS*(size_t)HID];
__device__ __nv_bfloat16 g_wqh[QKVD*(size_t)CDIM], g_wql[QKVD*(size_t)CDIM];
__device__ __nv_bfloat16 g_wph[CDIM*(size_t)CDIM], g_wpl[CDIM*(size_t)CDIM];
__device__ __nv_bfloat16 g_w1h[HID*(size_t)CDIM],  g_w1l[HID*(size_t)CDIM];
__device__ __nv_bfloat16 g_w2h[CDIM*(size_t)HID],  g_w2l[CDIM*(size_t)HID];

// ---------------- helpers ----------------
__device__ __forceinline__ uint32_t smem_u32(const void* p) {
    uint32_t a;
    asm("{ .reg .u64 t; cvta.to.shared.u64 t, %1; cvt.u32.u64 %0, t; }" : "=r"(a) : "l"(p));
    return a;
}
__device__ __forceinline__ void cpa16(uint32_t dst, const void* src) {
    asm volatile("cp.async.cg.shared.global [%0], [%1], 16;" :: "r"(dst), "l"(src));
}
#define CP_COMMIT() asm volatile("cp.async.commit_group;" ::: "memory")
#define CP_WAIT2()  asm volatile("cp.async.wait_group 2;" ::: "memory")

#define LDX4(r, addr) \
    asm volatile("ldmatrix.sync.aligned.m8n8.x4.shared.b16 {%0,%1,%2,%3}, [%4];" \
        : "=r"((r)[0]), "=r"((r)[1]), "=r"((r)[2]), "=r"((r)[3]) : "r"(addr))

#define HMMA(c, a, b0, b1) \
    asm volatile("mma.sync.aligned.m16n8k16.row.col.f32.bf16.bf16.f32 " \
        "{%0,%1,%2,%3}, {%4,%5,%6,%7}, {%8,%9}, {%0,%1,%2,%3};" \
        : "+f"((c)[0]), "+f"((c)[1]), "+f"((c)[2]), "+f"((c)[3]) \
        : "r"((a)[0]), "r"((a)[1]), "r"((a)[2]), "r"((a)[3]), "r"(b0), "r"(b1))

__device__ __forceinline__ uint32_t pack2(__nv_bfloat16 a, __nv_bfloat16 b) {
    __nv_bfloat162 t; t.x = a; t.y = b; return *reinterpret_cast<uint32_t*>(&t);
}
__device__ __forceinline__ void split_f(float v, __nv_bfloat16& h, __nv_bfloat16& l) {
    h = __float2bfloat16_rn(v);
    l = __float2bfloat16_rn(v - __bfloat162float(h));
}
__device__ __forceinline__ float gelu_f(float x) {
    return 0.5f * x * (1.f + erff(x * 0.70710678118654752f));
}

// ---- fp32 -> bf16 hi/lo (weights) ----
__global__ void cvt_kernel(const float4* __restrict__ w, uint2* __restrict__ hi,
                           uint2* __restrict__ lo, int n4) {
    const int i = blockIdx.x * blockDim.x + threadIdx.x;
    if (i >= n4) return;
    const float4 v = w[i];
    __nv_bfloat16 h0,l0,h1,l1,h2,l2,h3,l3;
    split_f(v.x,h0,l0); split_f(v.y,h1,l1); split_f(v.z,h2,l2); split_f(v.w,h3,l3);
    hi[i] = make_uint2(pack2(h0,h1), pack2(h2,h3));
    lo[i] = make_uint2(pack2(l0,l1), pack2(l2,l3));
}

// ---- LayerNorm: fp32 in -> bf16 hi/lo out ----
__global__ void ln_kernel(const float* __restrict__ x, const float* __restrict__ g,
                          const float* __restrict__ b,
                          uint2* __restrict__ yh, uint2* __restrict__ yl) {
    __shared__ float red[64];
    const int row = blockIdx.x, tid = threadIdx.x;
    const float4 v = reinterpret_cast<const float4*>(x + (size_t)row * CDIM)[tid];
    float s = v.x+v.y+v.z+v.w, sq = v.x*v.x+v.y*v.y+v.z*v.z+v.w*v.w;
    #pragma unroll
    for (int m = 16; m; m >>= 1) {
        s  += __shfl_xor_sync(0xffffffffu, s,  m);
        sq += __shfl_xor_sync(0xffffffffu, sq, m);
    }
    const int warp = tid >> 5, lane = tid & 31;
    if (lane == 0) { red[warp] = s; red[warp + 8] = sq; }
    __syncthreads();
    if (tid < 32) {
        float a = (tid < 8) ? red[tid] : 0.f, c = (tid < 8) ? red[tid + 8] : 0.f;
        #pragma unroll
        for (int m = 4; m; m >>= 1) {
            a += __shfl_xor_sync(0xffffffffu, a, m);
            c += __shfl_xor_sync(0xffffffffu, c, m);
        }
        if (tid == 0) { red[0] = a; red[1] = c; }
    }
    __syncthreads();
    const float mean = red[0] * (1.f/CDIM);
    const float rstd = rsqrtf(red[1] * (1.f/CDIM) - mean*mean + 1e-5f);
    const float4 gv = reinterpret_cast<const float4*>(g)[tid];
    const float4 bv = reinterpret_cast<const float4*>(b)[tid];
    float o0 = (v.x-mean)*rstd*gv.x+bv.x, o1 = (v.y-mean)*rstd*gv.y+bv.y;
    float o2 = (v.z-mean)*rstd*gv.z+bv.z, o3 = (v.w-mean)*rstd*gv.w+bv.w;
    __nv_bfloat16 h0,l0,h1,l1,h2,l2,h3,l3;
    split_f(o0,h0,l0); split_f(o1,h1,l1); split_f(o2,h2,l2); split_f(o3,h3,l3);
    yh[(size_t)row * (CDIM/4) + tid] = make_uint2(pack2(h0,h1), pack2(h2,h3));
    yl[(size_t)row * (CDIM/4) + tid] = make_uint2(pack2(l0,l1), pack2(l2,l3));
}

// ---- bf16 split-precision GEMM NT via mma.sync (HMMA) ----
// C[M,N] = A @ W^T, inputs as bf16 hi/lo. 128x128 tile, 16 warps (4x4),
// warp tile 32x32, k-step 32, 3-stage cp.async pipeline, 80B smem row stride.
// EPI: 0 plain fp32 out; 1 bias+GELU -> bf16 hi/lo out; 2 bias+residual fp32.
#define STG_B 40960              // bytes per stage: 4 tiles * 128 rows * 80B
#define TIL_B 10240              // bytes per tile (128 rows * 80B)
#define GSMEM (3 * STG_B)

template <int EPI>
__global__ __launch_bounds__(512)
void gemm_bf(const __nv_bfloat16* __restrict__ Ah, const __nv_bfloat16* __restrict__ Al,
             const __nv_bfloat16* __restrict__ Bh, const __nv_bfloat16* __restrict__ Bl,
             const float* __restrict__ bias, const float* __restrict__ res,
             float* __restrict__ Cout,
             __nv_bfloat16* __restrict__ Oh, __nv_bfloat16* __restrict__ Ol,
             int N, int K) {
    extern __shared__ char dynsm[];
    const uint32_t sb0 = smem_u32(dynsm);
    const int tid = threadIdx.x, wid = tid >> 5, lane = tid & 31;
    const int warp_m = wid >> 2, warp_n = wid & 3;   // 4x4 warp grid, 32x32 tiles
    const int bm = blockIdx.y * 128, bn = blockIdx.x * 128;

    // loader: 1 thread per (tile,row); each thread 4x16B chunks (64B data of row)
    const int ltile = tid >> 7;     // 0..3: Ah, Al, Bh, Bl
    const int lrow  = tid & 127;
    const __nv_bfloat16* lsrc =
        (ltile == 0) ? Ah + (size_t)(bm + lrow) * K :
        (ltile == 1) ? Al + (size_t)(bm + lrow) * K :
        (ltile == 2) ? Bh + (size_t)(bn + lrow) * K :
                       Bl + (size_t)(bn + lrow) * K;
    const uint32_t ldst = ltile * TIL_B + lrow * 80;

    float c[2][4][4];
    #pragma unroll
    for (int a = 0; a < 2; a++)
        #pragma unroll
        for (int b = 0; b < 4; b++)
            #pragma unroll
            for (int q = 0; q < 4; q++) c[a][b][q] = 0.f;

    const int NK = K >> 5;
    // prologue: stages 0..2
    #pragma unroll
    for (int s = 0; s < 3; s++) {
        const uint32_t sb = sb0 + s * STG_B + ldst;
        #pragma unroll
        for (int ch = 0; ch < 4; ch++)
            cpa16(sb + ch * 16, lsrc + (size_t)s * 32 + ch * 8);
        CP_COMMIT();
    }

    // per-thread ldmatrix base offsets (within a stage)
    const uint32_t aOffH = (warp_m * 32 + (lane & 15)) * 80 + (lane >> 4) * 16;
    const uint32_t aOffL = aOffH + TIL_B;
    const uint32_t bOffH = 2 * TIL_B + (warp_n * 32 + (lane & 15)) * 80 + (lane >> 4) * 16;
    const uint32_t bOffL = bOffH + TIL_B;

    for (int i = 0; i < NK; i++) {
        CP_WAIT2();
        __syncthreads();
        const uint32_t sb = sb0 + (i % 3) * STG_B;
        #pragma unroll
        for (int k16 = 0; k16 < 2; k16++) {
            const uint32_t ko = k16 * 32;  // 16 bf16 = 32B
            uint32_t ahf[2][4], alf[2][4], bhf[2][4], blf[2][4];
            #pragma unroll
            for (int g = 0; g < 2; g++) {
                LDX4(bhf[g], sb + bOffH + ko + g * 16 * 80);
                LDX4(blf[g], sb + bOffL + ko + g * 16 * 80);
            }
            #pragma unroll
            for (int mf = 0; mf < 2; mf++) {
                LDX4(ahf[mf], sb + aOffH + ko + mf * 16 * 80);
                LDX4(alf[mf], sb + aOffL + ko + mf * 16 * 80);
            }
            #pragma unroll
            for (int mf = 0; mf < 2; mf++)
                #pragma unroll
                for (int nf = 0; nf < 4; nf++) {
                    const int g = nf >> 1, p = nf & 1;
                    HMMA(c[mf][nf], ahf[mf], bhf[g][0 + p], bhf[g][2 + p]);
                    HMMA(c[mf][nf], ahf[mf], blf[g][0 + p], blf[g][2 + p]);
                    HMMA(c[mf][nf], alf[mf], bhf[g][0 + p], bhf[g][2 + p]);
                }
        }
        __syncthreads();
        if (i + 3 < NK) {
            const uint32_t sbw = sb0 + (i % 3) * STG_B + ldst;
            #pragma unroll
            for (int ch = 0; ch < 4; ch++)
                cpa16(sbw + ch * 16, lsrc + (size_t)(i + 3) * 32 + ch * 8);
        }
        CP_COMMIT();
    }

    // ---- epilogue ----
    #pragma unroll
    for (int mf = 0; mf < 2; mf++) {
        const int r0 = bm + warp_m * 32 + mf * 16 + (lane >> 2);
        #pragma unroll
        for (int nf = 0; nf < 4; nf++) {
            const int col = bn + warp_n * 32 + nf * 8 + (lane & 3) * 2;
            float v0 = c[mf][nf][0], v1 = c[mf][nf][1];
            float v2 = c[mf][nf][2], v3 = c[mf][nf][3];
            if (EPI != 0) {
                const float2 bb = *(const float2*)(bias + col);
                v0 += bb.x; v1 += bb.y; v2 += bb.x; v3 += bb.y;
            }
            if (EPI == 1) {
                v0 = gelu_f(v0); v1 = gelu_f(v1); v2 = gelu_f(v2); v3 = gelu_f(v3);
                __nv_bfloat16 h0,l0,h1,l1,h2,l2,h3,l3;
                split_f(v0,h0,l0); split_f(v1,h1,l1);
                split_f(v2,h2,l2); split_f(v3,h3,l3);
                *(uint32_t*)(Oh + (size_t)r0 * N + col)       = pack2(h0, h1);
                *(uint32_t*)(Ol + (size_t)r0 * N + col)       = pack2(l0, l1);
                *(uint32_t*)(Oh + (size_t)(r0 + 8) * N + col) = pack2(h2, h3);
                *(uint32_t*)(Ol + (size_t)(r0 + 8) * N + col) = pack2(l2, l3);
            } else {
                if (EPI == 2) {
                    const float2 ra = *(const float2*)(res + (size_t)r0 * N + col);
                    const float2 rb = *(const float2*)(res + (size_t)(r0 + 8) * N + col);
                    v0 += ra.x; v1 += ra.y; v2 += rb.x; v3 += rb.y;
                }
                *(float2*)(Cout + (size_t)r0 * N + col)       = make_float2(v0, v1);
                *(float2*)(Cout + (size_t)(r0 + 8) * N + col) = make_float2(v2, v3);
            }
        }
    }
}

// ---- fused attention (flash-style, fp32 compute, bf16 hi/lo out) ----
__global__ __launch_bounds__(256)
void attn_kernel(const float* __restrict__ qkv,
                 __nv_bfloat16* __restrict__ oh, __nv_bfloat16* __restrict__ ol) {
    __shared__ float Qst [64 * 64];
    __shared__ float KPst[64 * 64];
    __shared__ float Vs  [64 * 64];
    const int b = blockIdx.z, h = blockIdx.y, q0 = blockIdx.x * 64;
    const int tid = threadIdx.x;
    const int tr = tid >> 4, tc = tid & 15, lr = tid >> 2, lc = tid & 3;
    const size_t base = (size_t)b * SEQ * QKVD + (size_t)h * HD;
    {
        const float* qrow = qkv + base + (size_t)(q0 + lr) * QKVD;
        #pragma unroll
        for (int c = 0; c < 4; c++) {
            const int d = lc * 16 + c * 4;
            const float4 v = *(const float4*)(qrow + d);
            Qst[(d+0)*64+lr] = v.x*0.125f; Qst[(d+1)*64+lr] = v.y*0.125f;
            Qst[(d+2)*64+lr] = v.z*0.125f; Qst[(d+3)*64+lr] = v.w*0.125f;
        }
    }
    float acc[4][4];
    #pragma unroll
    for (int i = 0; i < 4; i++)
        #pragma unroll
        for (int j = 0; j < 4; j++) acc[i][j] = 0.f;
    float m_i[4], l_i[4];
    #pragma unroll
    for (int i = 0; i < 4; i++) { m_i[i] = -1e30f; l_i[i] = 0.f; }

    for (int kt = 0; kt < SEQ; kt += 64) {
        __syncthreads();
        {
            const float* krow = qkv + base + CDIM     + (size_t)(kt + lr) * QKVD;
            const float* vrow = qkv + base + 2 * CDIM + (size_t)(kt + lr) * QKVD;
            #pragma unroll
            for (int c = 0; c < 4; c++) {
                const int d = lc * 16 + c * 4;
                const float4 kv = *(const float4*)(krow + d);
                KPst[(d+0)*64+lr] = kv.x; KPst[(d+1)*64+lr] = kv.y;
                KPst[(d+2)*64+lr] = kv.z; KPst[(d+3)*64+lr] = kv.w;
                *(float4*)&Vs[lr * 64 + d] = *(const float4*)(vrow + d);
            }
        }
        __syncthreads();
        float s[4][4];
        #pragma unroll
        for (int i = 0; i < 4; i++)
            #pragma unroll
            for (int j = 0; j < 4; j++) s[i][j] = 0.f;
        #pragma unroll
        for (int d = 0; d < 64; d++) {
            const float4 q = *(const float4*)&Qst [d * 64 + tr * 4];
            const float4 k = *(const float4*)&KPst[d * 64 + tc * 4];
            const float qa[4] = {q.x,q.y,q.z,q.w}, ka[4] = {k.x,k.y,k.z,k.w};
            #pragma unroll
            for (int i = 0; i < 4; i++)
                #pragma unroll
                for (int j = 0; j < 4; j++) s[i][j] += qa[i] * ka[j];
        }
        #pragma unroll
        for (int i = 0; i < 4; i++) {
            float mx = fmaxf(fmaxf(s[i][0], s[i][1]), fmaxf(s[i][2], s[i][3]));
            mx = fmaxf(mx, __shfl_xor_sync(0xffffffffu, mx, 1));
            mx = fmaxf(mx, __shfl_xor_sync(0xffffffffu, mx, 2));
            mx = fmaxf(mx, __shfl_xor_sync(0xffffffffu, mx, 4));
            mx = fmaxf(mx, __shfl_xor_sync(0xffffffffu, mx, 8));
            const float newm = fmaxf(m_i[i], mx);
            const float alpha = __expf(m_i[i] - newm);
            m_i[i] = newm;
            float rs = 0.f;
            #pragma unroll
            for (int j = 0; j < 4; j++) { const float p = __expf(s[i][j] - newm); s[i][j] = p; rs += p; }
            rs += __shfl_xor_sync(0xffffffffu, rs, 1);
            rs += __shfl_xor_sync(0xffffffffu, rs, 2);
            rs += __shfl_xor_sync(0xffffffffu, rs, 4);
            rs += __shfl_xor_sync(0xffffffffu, rs, 8);
            l_i[i] = l_i[i] * alpha + rs;
            #pragma unroll
            for (int j = 0; j < 4; j++) acc[i][j] *= alpha;
        }
        __syncthreads();
        #pragma unroll
        for (int j = 0; j < 4; j++) {
            const int k = tc * 4 + j;
            *(float4*)&KPst[k * 64 + ((tr * 4) ^ ((tc & 7) * 4))] =
                make_float4(s[0][j], s[1][j], s[2][j], s[3][j]);
        }
        __syncthreads();
        #pragma unroll
        for (int k = 0; k < 64; k++) {
            const float4 p = *(const float4*)&KPst[k * 64 + ((tr * 4) ^ (((k >> 2) & 7) * 4))];
            const float4 v = *(const float4*)&Vs[k * 64 + tc * 4];
            const float pa[4] = {p.x,p.y,p.z,p.w}, va[4] = {v.x,v.y,v.z,v.w};
            #pragma unroll
            for (int i = 0; i < 4; i++)
                #pragma unroll
                for (int j = 0; j < 4; j++) acc[i][j] += pa[i] * va[j];
        }
    }
    #pragma unroll
    for (int i = 0; i < 4; i++) {
        const float inv = 1.f / l_i[i];
        const size_t row = (size_t)(b * SEQ + q0 + tr * 4 + i);
        const size_t o0 = row * CDIM + h * HD + tc * 4;
        __nv_bfloat16 h0,l0,h1,l1,h2,l2,h3,l3;
        split_f(acc[i][0]*inv, h0, l0); split_f(acc[i][1]*inv, h1, l1);
        split_f(acc[i][2]*inv, h2, l2); split_f(acc[i][3]*inv, h3, l3);
        *(uint2*)(oh + o0) = make_uint2(pack2(h0,h1), pack2(h2,h3));
        *(uint2*)(ol + o0) = make_uint2(pack2(l0,l1), pack2(l2,l3));
    }
}

// ---------------- launch ----------------
extern "C" void kernel_launch(void* const* d_in, const int* in_sizes, int n_in,
                              void* d_out, int out_size) {
    const float* x      = (const float*)d_in[0];
    const float* b_proj = (const float*)d_in[3];
    const float* ln1_g  = (const float*)d_in[4];
    const float* ln1_b  = (const float*)d_in[5];
    const float* ln2_g  = (const float*)d_in[6];
    const float* ln2_b  = (const float*)d_in[7];
    const float* b_fc1  = (const float*)d_in[9];
    const float* b_fc2  = (const float*)d_in[11];
    float* out = (float*)d_out;

    void *qkv, *x1, *yh, *yl, *ah, *al, *hh, *hl, *fh, *fl;
    void *wqh, *wql, *wph, *wpl, *w1h, *w1l, *w2h, *w2l;
    cudaGetSymbolAddress(&qkv, g_qkv); cudaGetSymbolAddress(&x1, g_x1);
    cudaGetSymbolAddress(&yh, g_yh); cudaGetSymbolAddress(&yl, g_yl);
    cudaGetSymbolAddress(&ah, g_ah); cudaGetSymbolAddress(&al, g_al);
    cudaGetSymbolAddress(&hh, g_hh); cudaGetSymbolAddress(&hl, g_hl);
    cudaGetSymbolAddress(&fh, g_fh); cudaGetSymbolAddress(&fl, g_fl);
    cudaGetSymbolAddress(&wqh, g_wqh); cudaGetSymbolAddress(&wql, g_wql);
    cudaGetSymbolAddress(&wph, g_wph); cudaGetSymbolAddress(&wpl, g_wpl);
    cudaGetSymbolAddress(&w1h, g_w1h); cudaGetSymbolAddress(&w1l, g_w1l);
    cudaGetSymbolAddress(&w2h, g_w2h); cudaGetSymbolAddress(&w2l, g_w2l);

    cudaFuncSetAttribute(gemm_bf<0>, cudaFuncAttributeMaxDynamicSharedMemorySize, GSMEM);
    cudaFuncSetAttribute(gemm_bf<1>, cudaFuncAttributeMaxDynamicSharedMemorySize, GSMEM);
    cudaFuncSetAttribute(gemm_bf<2>, cudaFuncAttributeMaxDynamicSharedMemorySize, GSMEM);

    // weights -> hi/lo
    cvt_kernel<<<QKVD*CDIM/1024, 256>>>((const float4*)d_in[1], (uint2*)wqh, (uint2*)wql, QKVD*CDIM/4);
    cvt_kernel<<<CDIM*CDIM/1024, 256>>>((const float4*)d_in[2], (uint2*)wph, (uint2*)wpl, CDIM*CDIM/4);
    cvt_kernel<<<HID*CDIM/1024, 256>>>((const float4*)d_in[8], (uint2*)w1h, (uint2*)w1l, HID*CDIM/4);
    cvt_kernel<<<CDIM*HID/1024, 256>>>((const float4*)d_in[10], (uint2*)w2h, (uint2*)w2l, CDIM*HID/4);

    // 1) ln1 -> hi/lo
    ln_kernel<<<MROWS, 256>>>(x, ln1_g, ln1_b, (uint2*)yh, (uint2*)yl);
    // 2) qkv = y @ w_qkv^T  (fp32 out)
    gemm_bf<0><<<dim3(QKVD/128, MROWS/128), 512, GSMEM>>>(
        (const __nv_bfloat16*)yh, (const __nv_bfloat16*)yl,
        (const __nv_bfloat16*)wqh, (const __nv_bfloat16*)wql,
        nullptr, nullptr, (float*)qkv, nullptr, nullptr, QKVD, CDIM);
    // 3) attention -> hi/lo
    attn_kernel<<<dim3(SEQ/64, NHEAD, 2), 256>>>(
        (const float*)qkv, (__nv_bfloat16*)ah, (__nv_bfloat16*)al);
    // 4) x1 = x + att @ w_proj^T + b_proj
    gemm_bf<2><<<dim3(CDIM/128, MROWS/128), 512, GSMEM>>>(
        (const __nv_bfloat16*)ah, (const __nv_bfloat16*)al,
        (const __nv_bfloat16*)wph, (const __nv_bfloat16*)wpl,
        b_proj, x, (float*)x1, nullptr, nullptr, CDIM, CDIM);
    // 5) ln2 -> hi/lo
    ln_kernel<<<MROWS, 256>>>((const float*)x1, ln2_g, ln2_b, (uint2*)hh, (uint2*)hl);
    // 6) f1 = gelu(h @ w_fc1^T + b_fc1) -> hi/lo
    gemm_bf<1><<<dim3(HID/128, MROWS/128), 512, GSMEM>>>(
        (const __nv_bfloat16*)hh, (const __nv_bfloat16*)hl,
        (const __nv_bfloat16*)w1h, (const __nv_bfloat16*)w1l,
        b_fc1, nullptr, nullptr, (__nv_bfloat16*)fh, (__nv_bfloat16*)fl, HID, CDIM);
    // 7) out = x1 + f1 @ w_fc2^T + b_fc2
    gemm_bf<2><<<dim3(CDIM/128, MROWS/128), 512, GSMEM>>>(
        (const __nv_bfloat16*)fh, (const __nv_bfloat16*)fl,
        (const __nv_bfloat16*)w2h, (const __nv_bfloat16*)w2l,
        b_fc2, (const float*)x1, out, nullptr, nullptr, CDIM, HID);
}

// round 9
// speedup vs baseline: 1.1008x; 1.1008x over previous
#include <cuda_runtime.h>
#include <cuda_bf16.h>
#include <cstdint>
#include <math.h>

#define MROWS 4096
#define CDIM  1024
#define QKVD  3072
#define HID   4096
#define SEQ   2048
#define NHEAD 16
#define HD    64

// ---------------- scratch ----------------
__device__ float g_qkv[MROWS * (size_t)QKVD];
__device__ float g_x1 [MROWS * (size_t)CDIM];
__device__ __nv_bfloat16 g_yh[MROWS*(size_t)CDIM], g_yl[MROWS*(size_t)CDIM];
__device__ __nv_bfloat16 g_ah[MROWS*(size_t)CDIM], g_al[MROWS*(size_t)CDIM];
__device__ __nv_bfloat16 g_hh[MROWS*(size_t)CDIM], g_hl[MROWS*(size_t)CDIM];
__device__ __nv_bfloat16 g_fh[MROWS*(size_t)HID],  g_fl[MROWS*(size_t)HID];
__device__ __nv_bfloat16 g_wqh[QKVD*(size_t)CDIM], g_wql[QKVD*(size_t)CDIM];
__device__ __nv_bfloat16 g_wph[CDIM*(size_t)CDIM], g_wpl[CDIM*(size_t)CDIM];
__device__ __nv_bfloat16 g_w1h[HID*(size_t)CDIM],  g_w1l[HID*(size_t)CDIM];
__device__ __nv_bfloat16 g_w2h[CDIM*(size_t)HID],  g_w2l[CDIM*(size_t)HID];

// ---------------- helpers ----------------
__device__ __forceinline__ uint32_t smem_u32(const void* p) {
    uint32_t a;
    asm("{ .reg .u64 t; cvta.to.shared.u64 t, %1; cvt.u32.u64 %0, t; }" : "=r"(a) : "l"(p));
    return a;
}
__device__ __forceinline__ void cpa16(uint32_t dst, const void* src) {
    asm volatile("cp.async.cg.shared.global [%0], [%1], 16;" :: "r"(dst), "l"(src));
}
#define CP_COMMIT() asm volatile("cp.async.commit_group;" ::: "memory")
#define CP_WAIT2()  asm volatile("cp.async.wait_group 2;" ::: "memory")

#define LDX4(r, addr) \
    asm volatile("ldmatrix.sync.aligned.m8n8.x4.shared.b16 {%0,%1,%2,%3}, [%4];" \
        : "=r"((r)[0]), "=r"((r)[1]), "=r"((r)[2]), "=r"((r)[3]) : "r"(addr))

#define HMMA(c, a, b0, b1) \
    asm volatile("mma.sync.aligned.m16n8k16.row.col.f32.bf16.bf16.f32 " \
        "{%0,%1,%2,%3}, {%4,%5,%6,%7}, {%8,%9}, {%0,%1,%2,%3};" \
        : "+f"((c)[0]), "+f"((c)[1]), "+f"((c)[2]), "+f"((c)[3]) \
        : "r"((a)[0]), "r"((a)[1]), "r"((a)[2]), "r"((a)[3]), "r"(b0), "r"(b1))

__device__ __forceinline__ uint32_t pack2(__nv_bfloat16 a, __nv_bfloat16 b) {
    __nv_bfloat162 t; t.x = a; t.y = b; return *reinterpret_cast<uint32_t*>(&t);
}
__device__ __forceinline__ void split_f(float v, __nv_bfloat16& h, __nv_bfloat16& l) {
    h = __float2bfloat16_rn(v);
    l = __float2bfloat16_rn(v - __bfloat162float(h));
}
__device__ __forceinline__ float gelu_f(float x) {
    return 0.5f * x * (1.f + erff(x * 0.70710678118654752f));
}

// ---- fp32 -> bf16 hi/lo (weights) ----
__global__ void cvt_kernel(const float4* __restrict__ w, uint2* __restrict__ hi,
                           uint2* __restrict__ lo, int n4) {
    const int i = blockIdx.x * blockDim.x + threadIdx.x;
    if (i >= n4) return;
    const float4 v = w[i];
    __nv_bfloat16 h0,l0,h1,l1,h2,l2,h3,l3;
    split_f(v.x,h0,l0); split_f(v.y,h1,l1); split_f(v.z,h2,l2); split_f(v.w,h3,l3);
    hi[i] = make_uint2(pack2(h0,h1), pack2(h2,h3));
    lo[i] = make_uint2(pack2(l0,l1), pack2(l2,l3));
}

// ---- LayerNorm: fp32 in -> bf16 hi/lo out ----
__global__ void ln_kernel(const float* __restrict__ x, const float* __restrict__ g,
                          const float* __restrict__ b,
                          uint2* __restrict__ yh, uint2* __restrict__ yl) {
    __shared__ float red[64];
    const int row = blockIdx.x, tid = threadIdx.x;
    const float4 v = reinterpret_cast<const float4*>(x + (size_t)row * CDIM)[tid];
    float s = v.x+v.y+v.z+v.w, sq = v.x*v.x+v.y*v.y+v.z*v.z+v.w*v.w;
    #pragma unroll
    for (int m = 16; m; m >>= 1) {
        s  += __shfl_xor_sync(0xffffffffu, s,  m);
        sq += __shfl_xor_sync(0xffffffffu, sq, m);
    }
    const int warp = tid >> 5, lane = tid & 31;
    if (lane == 0) { red[warp] = s; red[warp + 8] = sq; }
    __syncthreads();
    if (tid < 32) {
        float a = (tid < 8) ? red[tid] : 0.f, c = (tid < 8) ? red[tid + 8] : 0.f;
        #pragma unroll
        for (int m = 4; m; m >>= 1) {
            a += __shfl_xor_sync(0xffffffffu, a, m);
            c += __shfl_xor_sync(0xffffffffu, c, m);
        }
        if (tid == 0) { red[0] = a; red[1] = c; }
    }
    __syncthreads();
    const float mean = red[0] * (1.f/CDIM);
    const float rstd = rsqrtf(red[1] * (1.f/CDIM) - mean*mean + 1e-5f);
    const float4 gv = reinterpret_cast<const float4*>(g)[tid];
    const float4 bv = reinterpret_cast<const float4*>(b)[tid];
    float o0 = (v.x-mean)*rstd*gv.x+bv.x, o1 = (v.y-mean)*rstd*gv.y+bv.y;
    float o2 = (v.z-mean)*rstd*gv.z+bv.z, o3 = (v.w-mean)*rstd*gv.w+bv.w;
    __nv_bfloat16 h0,l0,h1,l1,h2,l2,h3,l3;
    split_f(o0,h0,l0); split_f(o1,h1,l1); split_f(o2,h2,l2); split_f(o3,h3,l3);
    yh[(size_t)row * (CDIM/4) + tid] = make_uint2(pack2(h0,h1), pack2(h2,h3));
    yl[(size_t)row * (CDIM/4) + tid] = make_uint2(pack2(l0,l1), pack2(l2,l3));
}

// ---- bf16 split-precision GEMM NT via mma.sync (HMMA) ----
// C[M,N] = A @ W^T, inputs as bf16 hi/lo. 128x128 tile, 8 warps (2x4),
// warp tile 64x32, k-step 32, 4-stage cp.async pipeline (ONE barrier/iter),
// 80B smem row stride. HMMA issued product-major for 16-deep acc ILP.
// EPI: 0 plain fp32 out; 1 bias+GELU -> bf16 hi/lo out; 2 bias+residual fp32.
#define STG_B 40960              // bytes per stage: 4 tiles * 128 rows * 80B
#define TIL_B 10240              // bytes per tile (128 rows * 80B)
#define GSMEM (4 * STG_B)        // 160 KB

template <int EPI>
__global__ __launch_bounds__(256)
void gemm_bf(const __nv_bfloat16* __restrict__ Ah, const __nv_bfloat16* __restrict__ Al,
             const __nv_bfloat16* __restrict__ Bh, const __nv_bfloat16* __restrict__ Bl,
             const float* __restrict__ bias, const float* __restrict__ res,
             float* __restrict__ Cout,
             __nv_bfloat16* __restrict__ Oh, __nv_bfloat16* __restrict__ Ol,
             int N, int K) {
    extern __shared__ char dynsm[];
    const uint32_t sb0 = smem_u32(dynsm);
    const int tid = threadIdx.x, wid = tid >> 5, lane = tid & 31;
    const int warp_m = wid >> 2, warp_n = wid & 3;   // 2x4 grid, 64x32 tiles
    const int bm = blockIdx.y * 128, bn = blockIdx.x * 128;

    // loader: 2 threads per row; each thread 2x16B chunks per tile
    const int lrow = tid >> 1;
    const int lch  = (tid & 1) * 2;
    const __nv_bfloat16* gA[4] = {
        Ah + (size_t)(bm + lrow) * K + lch * 8,
        Al + (size_t)(bm + lrow) * K + lch * 8,
        Bh + (size_t)(bn + lrow) * K + lch * 8,
        Bl + (size_t)(bn + lrow) * K + lch * 8 };
    const uint32_t ldst = lrow * 80 + lch * 16;

    float c[4][4][4];
    #pragma unroll
    for (int a = 0; a < 4; a++)
        #pragma unroll
        for (int b = 0; b < 4; b++)
            #pragma unroll
            for (int q = 0; q < 4; q++) c[a][b][q] = 0.f;

    const int NK = K >> 5;
    // prologue: chunks 0..2 into stages 0..2 (3 groups in flight)
    #pragma unroll
    for (int s = 0; s < 3; s++) {
        const uint32_t sb = sb0 + s * STG_B;
        #pragma unroll
        for (int t = 0; t < 4; t++) {
            cpa16(sb + t * TIL_B + ldst,      gA[t] + (size_t)s * 32);
            cpa16(sb + t * TIL_B + ldst + 16, gA[t] + (size_t)s * 32 + 8);
        }
        CP_COMMIT();
    }

    // per-thread ldmatrix base offsets (within a stage)
    const uint32_t aOff = (warp_m * 64 + (lane & 15)) * 80 + (lane >> 4) * 16;
    const uint32_t bOff = (warp_n * 32 + (lane & 15)) * 80 + (lane >> 4) * 16;

    for (int i = 0; i < NK; i++) {
        CP_WAIT2();                 // chunk i arrived (<=2 groups pending)
        __syncthreads();            // + all warps done reading stage (i-1)%4
        // issue chunk i+3 into stage (i+3)%4 == (i-1)%4, overlapping compute
        if (i + 3 < NK) {
            const uint32_t sbw = sb0 + ((i + 3) & 3) * STG_B;
            #pragma unroll
            for (int t = 0; t < 4; t++) {
                cpa16(sbw + t * TIL_B + ldst,      gA[t] + (size_t)(i + 3) * 32);
                cpa16(sbw + t * TIL_B + ldst + 16, gA[t] + (size_t)(i + 3) * 32 + 8);
            }
        }
        CP_COMMIT();

        const uint32_t sb = sb0 + (i & 3) * STG_B;
        #pragma unroll
        for (int k16 = 0; k16 < 2; k16++) {
            const uint32_t ko = k16 * 32;  // 16 bf16 = 32B
            uint32_t ahf[4][4], alf[4][4], bhf[2][4], blf[2][4];
            #pragma unroll
            for (int g = 0; g < 2; g++) {
                LDX4(bhf[g], sb + 2 * TIL_B + bOff + ko + g * 16 * 80);
                LDX4(blf[g], sb + 3 * TIL_B + bOff + ko + g * 16 * 80);
            }
            #pragma unroll
            for (int mf = 0; mf < 4; mf++) {
                LDX4(ahf[mf], sb + aOff + ko + mf * 16 * 80);
                LDX4(alf[mf], sb + TIL_B + aOff + ko + mf * 16 * 80);
            }
            // product-major: 16 independent accumulators per pass
            #pragma unroll
            for (int mf = 0; mf < 4; mf++)
                #pragma unroll
                for (int nf = 0; nf < 4; nf++) {
                    const int g = nf >> 1, p = nf & 1;
                    HMMA(c[mf][nf], ahf[mf], bhf[g][0 + p], bhf[g][2 + p]);
                }
            #pragma unroll
            for (int mf = 0; mf < 4; mf++)
                #pragma unroll
                for (int nf = 0; nf < 4; nf++) {
                    const int g = nf >> 1, p = nf & 1;
                    HMMA(c[mf][nf], ahf[mf], blf[g][0 + p], blf[g][2 + p]);
                }
            #pragma unroll
            for (int mf = 0; mf < 4; mf++)
                #pragma unroll
                for (int nf = 0; nf < 4; nf++) {
                    const int g = nf >> 1, p = nf & 1;
                    HMMA(c[mf][nf], alf[mf], bhf[g][0 + p], bhf[g][2 + p]);
                }
        }
    }

    // ---- epilogue ----
    #pragma unroll
    for (int mf = 0; mf < 4; mf++) {
        const int r0 = bm + warp_m * 64 + mf * 16 + (lane >> 2);
        #pragma unroll
        for (int nf = 0; nf < 4; nf++) {
            const int col = bn + warp_n * 32 + nf * 8 + (lane & 3) * 2;
            float v0 = c[mf][nf][0], v1 = c[mf][nf][1];
            float v2 = c[mf][nf][2], v3 = c[mf][nf][3];
            if (EPI != 0) {
                const float2 bb = *(const float2*)(bias + col);
                v0 += bb.x; v1 += bb.y; v2 += bb.x; v3 += bb.y;
            }
            if (EPI == 1) {
                v0 = gelu_f(v0); v1 = gelu_f(v1); v2 = gelu_f(v2); v3 = gelu_f(v3);
                __nv_bfloat16 h0,l0,h1,l1,h2,l2,h3,l3;
                split_f(v0,h0,l0); split_f(v1,h1,l1);
                split_f(v2,h2,l2); split_f(v3,h3,l3);
                *(uint32_t*)(Oh + (size_t)r0 * N + col)       = pack2(h0, h1);
                *(uint32_t*)(Ol + (size_t)r0 * N + col)       = pack2(l0, l1);
                *(uint32_t*)(Oh + (size_t)(r0 + 8) * N + col) = pack2(h2, h3);
                *(uint32_t*)(Ol + (size_t)(r0 + 8) * N + col) = pack2(l2, l3);
            } else {
                if (EPI == 2) {
                    const float2 ra = *(const float2*)(res + (size_t)r0 * N + col);
                    const float2 rb = *(const float2*)(res + (size_t)(r0 + 8) * N + col);
                    v0 += ra.x; v1 += ra.y; v2 += rb.x; v3 += rb.y;
                }
                *(float2*)(Cout + (size_t)r0 * N + col)       = make_float2(v0, v1);
                *(float2*)(Cout + (size_t)(r0 + 8) * N + col) = make_float2(v2, v3);
            }
        }
    }
}

// ---- fused attention (flash-style, fp32 compute, bf16 hi/lo out) ----
__global__ __launch_bounds__(256)
void attn_kernel(const float* __restrict__ qkv,
                 __nv_bfloat16* __restrict__ oh, __nv_bfloat16* __restrict__ ol) {
    __shared__ float Qst [64 * 64];
    __shared__ float KPst[64 * 64];
    __shared__ float Vs  [64 * 64];
    const int b = blockIdx.z, h = blockIdx.y, q0 = blockIdx.x * 64;
    const int tid = threadIdx.x;
    const int tr = tid >> 4, tc = tid & 15, lr = tid >> 2, lc = tid & 3;
    const size_t base = (size_t)b * SEQ * QKVD + (size_t)h * HD;
    {
        const float* qrow = qkv + base + (size_t)(q0 + lr) * QKVD;
        #pragma unroll
        for (int c = 0; c < 4; c++) {
            const int d = lc * 16 + c * 4;
            const float4 v = *(const float4*)(qrow + d);
            Qst[(d+0)*64+lr] = v.x*0.125f; Qst[(d+1)*64+lr] = v.y*0.125f;
            Qst[(d+2)*64+lr] = v.z*0.125f; Qst[(d+3)*64+lr] = v.w*0.125f;
        }
    }
    float acc[4][4];
    #pragma unroll
    for (int i = 0; i < 4; i++)
        #pragma unroll
        for (int j = 0; j < 4; j++) acc[i][j] = 0.f;
    float m_i[4], l_i[4];
    #pragma unroll
    for (int i = 0; i < 4; i++) { m_i[i] = -1e30f; l_i[i] = 0.f; }

    for (int kt = 0; kt < SEQ; kt += 64) {
        __syncthreads();
        {
            const float* krow = qkv + base + CDIM     + (size_t)(kt + lr) * QKVD;
            const float* vrow = qkv + base + 2 * CDIM + (size_t)(kt + lr) * QKVD;
            #pragma unroll
            for (int c = 0; c < 4; c++) {
                const int d = lc * 16 + c * 4;
                const float4 kv = *(const float4*)(krow + d);
                KPst[(d+0)*64+lr] = kv.x; KPst[(d+1)*64+lr] = kv.y;
                KPst[(d+2)*64+lr] = kv.z; KPst[(d+3)*64+lr] = kv.w;
                *(float4*)&Vs[lr * 64 + d] = *(const float4*)(vrow + d);
            }
        }
        __syncthreads();
        float s[4][4];
        #pragma unroll
        for (int i = 0; i < 4; i++)
            #pragma unroll
            for (int j = 0; j < 4; j++) s[i][j] = 0.f;
        #pragma unroll
        for (int d = 0; d < 64; d++) {
            const float4 q = *(const float4*)&Qst [d * 64 + tr * 4];
            const float4 k = *(const float4*)&KPst[d * 64 + tc * 4];
            const float qa[4] = {q.x,q.y,q.z,q.w}, ka[4] = {k.x,k.y,k.z,k.w};
            #pragma unroll
            for (int i = 0; i < 4; i++)
                #pragma unroll
                for (int j = 0; j < 4; j++) s[i][j] += qa[i] * ka[j];
        }
        #pragma unroll
        for (int i = 0; i < 4; i++) {
            float mx = fmaxf(fmaxf(s[i][0], s[i][1]), fmaxf(s[i][2], s[i][3]));
            mx = fmaxf(mx, __shfl_xor_sync(0xffffffffu, mx, 1));
            mx = fmaxf(mx, __shfl_xor_sync(0xffffffffu, mx, 2));
            mx = fmaxf(mx, __shfl_xor_sync(0xffffffffu, mx, 4));
            mx = fmaxf(mx, __shfl_xor_sync(0xffffffffu, mx, 8));
            const float newm = fmaxf(m_i[i], mx);
            const float alpha = __expf(m_i[i] - newm);
            m_i[i] = newm;
            float rs = 0.f;
            #pragma unroll
            for (int j = 0; j < 4; j++) { const float p = __expf(s[i][j] - newm); s[i][j] = p; rs += p; }
            rs += __shfl_xor_sync(0xffffffffu, rs, 1);
            rs += __shfl_xor_sync(0xffffffffu, rs, 2);
            rs += __shfl_xor_sync(0xffffffffu, rs, 4);
            rs += __shfl_xor_sync(0xffffffffu, rs, 8);
            l_i[i] = l_i[i] * alpha + rs;
            #pragma unroll
            for (int j = 0; j < 4; j++) acc[i][j] *= alpha;
        }
        __syncthreads();
        #pragma unroll
        for (int j = 0; j < 4; j++) {
            const int k = tc * 4 + j;
            *(float4*)&KPst[k * 64 + ((tr * 4) ^ ((tc & 7) * 4))] =
                make_float4(s[0][j], s[1][j], s[2][j], s[3][j]);
        }
        __syncthreads();
        #pragma unroll
        for (int k = 0; k < 64; k++) {
            const float4 p = *(const float4*)&KPst[k * 64 + ((tr * 4) ^ (((k >> 2) & 7) * 4))];
            const float4 v = *(const float4*)&Vs[k * 64 + tc * 4];
            const float pa[4] = {p.x,p.y,p.z,p.w}, va[4] = {v.x,v.y,v.z,v.w};
            #pragma unroll
            for (int i = 0; i < 4; i++)
                #pragma unroll
                for (int j = 0; j < 4; j++) acc[i][j] += pa[i] * va[j];
        }
    }
    #pragma unroll
    for (int i = 0; i < 4; i++) {
        const float inv = 1.f / l_i[i];
        const size_t row = (size_t)(b * SEQ + q0 + tr * 4 + i);
        const size_t o0 = row * CDIM + h * HD + tc * 4;
        __nv_bfloat16 h0,l0,h1,l1,h2,l2,h3,l3;
        split_f(acc[i][0]*inv, h0, l0); split_f(acc[i][1]*inv, h1, l1);
        split_f(acc[i][2]*inv, h2, l2); split_f(acc[i][3]*inv, h3, l3);
        *(uint2*)(oh + o0) = make_uint2(pack2(h0,h1), pack2(h2,h3));
        *(uint2*)(ol + o0) = make_uint2(pack2(l0,l1), pack2(l2,l3));
    }
}

// ---------------- launch ----------------
extern "C" void kernel_launch(void* const* d_in, const int* in_sizes, int n_in,
                              void* d_out, int out_size) {
    const float* x      = (const float*)d_in[0];
    const float* b_proj = (const float*)d_in[3];
    const float* ln1_g  = (const float*)d_in[4];
    const float* ln1_b  = (const float*)d_in[5];
    const float* ln2_g  = (const float*)d_in[6];
    const float* ln2_b  = (const float*)d_in[7];
    const float* b_fc1  = (const float*)d_in[9];
    const float* b_fc2  = (const float*)d_in[11];
    float* out = (float*)d_out;

    void *qkv, *x1, *yh, *yl, *ah, *al, *hh, *hl, *fh, *fl;
    void *wqh, *wql, *wph, *wpl, *w1h, *w1l, *w2h, *w2l;
    cudaGetSymbolAddress(&qkv, g_qkv); cudaGetSymbolAddress(&x1, g_x1);
    cudaGetSymbolAddress(&yh, g_yh); cudaGetSymbolAddress(&yl, g_yl);
    cudaGetSymbolAddress(&ah, g_ah); cudaGetSymbolAddress(&al, g_al);
    cudaGetSymbolAddress(&hh, g_hh); cudaGetSymbolAddress(&hl, g_hl);
    cudaGetSymbolAddress(&fh, g_fh); cudaGetSymbolAddress(&fl, g_fl);
    cudaGetSymbolAddress(&wqh, g_wqh); cudaGetSymbolAddress(&wql, g_wql);
    cudaGetSymbolAddress(&wph, g_wph); cudaGetSymbolAddress(&wpl, g_wpl);
    cudaGetSymbolAddress(&w1h, g_w1h); cudaGetSymbolAddress(&w1l, g_w1l);
    cudaGetSymbolAddress(&w2h, g_w2h); cudaGetSymbolAddress(&w2l, g_w2l);

    cudaFuncSetAttribute(gemm_bf<0>, cudaFuncAttributeMaxDynamicSharedMemorySize, GSMEM);
    cudaFuncSetAttribute(gemm_bf<1>, cudaFuncAttributeMaxDynamicSharedMemorySize, GSMEM);
    cudaFuncSetAttribute(gemm_bf<2>, cudaFuncAttributeMaxDynamicSharedMemorySize, GSMEM);

    // weights -> hi/lo
    cvt_kernel<<<QKVD*CDIM/1024, 256>>>((const float4*)d_in[1], (uint2*)wqh, (uint2*)wql, QKVD*CDIM/4);
    cvt_kernel<<<CDIM*CDIM/1024, 256>>>((const float4*)d_in[2], (uint2*)wph, (uint2*)wpl, CDIM*CDIM/4);
    cvt_kernel<<<HID*CDIM/1024, 256>>>((const float4*)d_in[8], (uint2*)w1h, (uint2*)w1l, HID*CDIM/4);
    cvt_kernel<<<CDIM*HID/1024, 256>>>((const float4*)d_in[10], (uint2*)w2h, (uint2*)w2l, CDIM*HID/4);

    // 1) ln1 -> hi/lo
    ln_kernel<<<MROWS, 256>>>(x, ln1_g, ln1_b, (uint2*)yh, (uint2*)yl);
    // 2) qkv = y @ w_qkv^T  (fp32 out)
    gemm_bf<0><<<dim3(QKVD/128, MROWS/128), 256, GSMEM>>>(
        (const __nv_bfloat16*)yh, (const __nv_bfloat16*)yl,
        (const __nv_bfloat16*)wqh, (const __nv_bfloat16*)wql,
        nullptr, nullptr, (float*)qkv, nullptr, nullptr, QKVD, CDIM);
    // 3) attention -> hi/lo
    attn_kernel<<<dim3(SEQ/64, NHEAD, 2), 256>>>(
        (const float*)qkv, (__nv_bfloat16*)ah, (__nv_bfloat16*)al);
    // 4) x1 = x + att @ w_proj^T + b_proj
    gemm_bf<2><<<dim3(CDIM/128, MROWS/128), 256, GSMEM>>>(
        (const __nv_bfloat16*)ah, (const __nv_bfloat16*)al,
        (const __nv_bfloat16*)wph, (const __nv_bfloat16*)wpl,
        b_proj, x, (float*)x1, nullptr, nullptr, CDIM, CDIM);
    // 5) ln2 -> hi/lo
    ln_kernel<<<MROWS, 256>>>((const float*)x1, ln2_g, ln2_b, (uint2*)hh, (uint2*)hl);
    // 6) f1 = gelu(h @ w_fc1^T + b_fc1) -> hi/lo
    gemm_bf<1><<<dim3(HID/128, MROWS/128), 256, GSMEM>>>(
        (const __nv_bfloat16*)hh, (const __nv_bfloat16*)hl,
        (const __nv_bfloat16*)w1h, (const __nv_bfloat16*)w1l,
        b_fc1, nullptr, nullptr, (__nv_bfloat16*)fh, (__nv_bfloat16*)fl, HID, CDIM);
    // 7) out = x1 + f1 @ w_fc2^T + b_fc2
    gemm_bf<2><<<dim3(CDIM/128, MROWS/128), 256, GSMEM>>>(
        (const __nv_bfloat16*)fh, (const __nv_bfloat16*)fl,
        (const __nv_bfloat16*)w2h, (const __nv_bfloat16*)w2l,
        b_fc2, (const float*)x1, out, nullptr, nullptr, CDIM, HID);
}